// round 6
// baseline (speedup 1.0000x reference)
#include <cuda_runtime.h>
#include <cuda_fp16.h>
#include <cstdint>
#include <math.h>

#define BD 8192
#define CD 2048
#define STRIDE_H 40          // halves per feature row (32 used + 8 pad)
#define STRIDE_B 80          // bytes per row; 80*r mod 128 -> conflict-free

// fp16 hi/lo split features, K=32 storage [hi(16)|lo(16)|pad].
// dot = ah.bh + ah.bl + al.bh  (drops only al.bl ~ 2^-22)
__device__ __align__(16) __half gA[2 * BD * STRIDE_H];
__device__ __align__(16) __half gB[2 * CD * STRIDE_H];

__device__ __forceinline__ uint32_t smem_u32(const void* p) {
    uint32_t a;
    asm("{ .reg .u64 t; cvta.to.shared.u64 t, %1; cvt.u32.u64 %0, t; }" : "=r"(a) : "l"(p));
    return a;
}

// ---------------- Kernel 1: feature precompute ----------------
__global__ void qk_pre(const float* __restrict__ x, const float* __restrict__ c,
                       int B, int C) {
    int t = blockIdx.x * blockDim.x + threadIdx.x;
    if (t >= B + C) return;
    bool isB = t >= B;
    int row = isB ? t - B : t;
    const float* src = (isB ? c : x) + row * 8;

    float cv[8], sv[8];
    #pragma unroll
    for (int j = 0; j < 8; j++) sincosf(0.5f * src[j], &sv[j], &cv[j]);

    float pf[4][4];
    #pragma unroll
    for (int p = 0; p < 4; p++) {
        pf[p][0] = cv[2*p] * cv[2*p+1];
        pf[p][1] = cv[2*p] * sv[2*p+1];
        pf[p][2] = sv[2*p] * cv[2*p+1];
        pf[p][3] = sv[2*p] * sv[2*p+1];
    }

    #pragma unroll
    for (int g = 0; g < 2; g++) {
        __align__(16) __half rowv[STRIDE_H];
        #pragma unroll
        for (int a = 0; a < 4; a++) {
            #pragma unroll
            for (int b = 0; b < 4; b++) {
                float f = pf[2*g][a] * pf[2*g+1][b];
                __half hi = __float2half_rn(f);
                __half lo = __float2half_rn(f - __half2float(hi));
                int i = a * 4 + b;
                rowv[i]      = hi;
                rowv[16 + i] = lo;
            }
        }
        #pragma unroll
        for (int i = 32; i < STRIDE_H; i++) rowv[i] = __float2half_rn(0.f);

        __half* dst = (isB ? gB : gA) + ((size_t)g * (isB ? CD : BD) + row) * STRIDE_H;
        #pragma unroll
        for (int j = 0; j < 5; j++)
            ((uint4*)dst)[j] = ((const uint4*)rowv)[j];
    }
}

// ---------------- Kernel 2: HMMA tile kernel ----------------
// Block 128x128, 16 warps (512 thr), warp tile 16 rows x 64 cols, 2 CTAs/SM.
// Smem: A0 | A1 | B0 | B1, each 128 x 80B = 10240B. Total 40960B.
#define SM_A0 0
#define SM_A1 10240
#define SM_B0 20480
#define SM_B1 30720

__device__ __forceinline__ void ldm_x4(uint32_t* r, uint32_t addr) {
    asm volatile("ldmatrix.sync.aligned.m8n8.x4.shared.b16 {%0,%1,%2,%3}, [%4];"
                 : "=r"(r[0]), "=r"(r[1]), "=r"(r[2]), "=r"(r[3]) : "r"(addr));
}
__device__ __forceinline__ void mma16816(float* d, const uint32_t* a,
                                         uint32_t b0, uint32_t b1) {
    asm volatile(
        "mma.sync.aligned.m16n8k16.row.col.f32.f16.f16.f32 "
        "{%0,%1,%2,%3}, {%4,%5,%6,%7}, {%8,%9}, {%0,%1,%2,%3};"
        : "+f"(d[0]), "+f"(d[1]), "+f"(d[2]), "+f"(d[3])
        : "r"(a[0]), "r"(a[1]), "r"(a[2]), "r"(a[3]), "r"(b0), "r"(b1));
}

__global__ void __launch_bounds__(512, 2)
qk_hmma(float* __restrict__ out, int C) {
    __shared__ __align__(16) unsigned char sm[40960];
    const int tid = threadIdx.x, wid = tid >> 5, lane = tid & 31;
    const int row0 = blockIdx.y * 128, col0 = blockIdx.x * 128;

    // Tile copies: 640 uint4 per array, linear.
    {
        const uint4* s0 = (const uint4*)(gA + (size_t)row0 * STRIDE_H);
        const uint4* s1 = (const uint4*)(gA + (size_t)(BD + row0) * STRIDE_H);
        const uint4* s2 = (const uint4*)(gB + (size_t)col0 * STRIDE_H);
        const uint4* s3 = (const uint4*)(gB + (size_t)(CD + col0) * STRIDE_H);
        uint4* d0 = (uint4*)(sm + SM_A0);
        uint4* d1 = (uint4*)(sm + SM_A1);
        uint4* d2 = (uint4*)(sm + SM_B0);
        uint4* d3 = (uint4*)(sm + SM_B1);
        for (int i = tid; i < 640; i += 512) {
            d0[i] = s0[i]; d1[i] = s1[i]; d2[i] = s2[i]; d3[i] = s3[i];
        }
    }
    __syncthreads();

    const int wr = wid & 7;        // 8 row groups of 16
    const int wc = wid >> 3;       // 2 col groups of 64
    const uint32_t sb = smem_u32(sm);

    // Persistent a-frags: af[g][hl][4] (16 rows), 16 regs.
    uint32_t af[2][2][4];
    {
        const uint32_t aoff =
            (uint32_t)(wr * 16 + (lane & 15)) * STRIDE_B + (lane >> 4) * 16;
        #pragma unroll
        for (int hl = 0; hl < 2; hl++) {
            ldm_x4(af[0][hl], sb + SM_A0 + aoff + hl * 32);
            ldm_x4(af[1][hl], sb + SM_A1 + aoff + hl * 32);
        }
    }

    // B ldmatrix base: one x4 covers an nt-pair (16 cols) for one hi/lo half.
    const uint32_t boff =
        (uint32_t)(wc * 64 + (lane & 7) + ((lane >> 4) << 3)) * STRIDE_B +
        ((lane >> 3) & 1) * 16;
    const uint32_t bAddr0 = sb + SM_B0 + boff;
    const uint32_t bAddr1 = sb + SM_B1 + boff;

    const int colb = col0 + wc * 64 + (lane & 3) * 2;
    const size_t rbase = (size_t)(row0 + wr * 16 + (lane >> 2));

    #pragma unroll
    for (int np = 0; np < 4; np++) {   // 16-col chunks
        const uint32_t bo = np * 16 * STRIDE_B;

        // Load all b-frags up front: both groups, hi+lo (16 regs).
        uint32_t bh0[4], bl0[4], bh1[4], bl1[4];
        ldm_x4(bh0, bAddr0 + bo);
        ldm_x4(bl0, bAddr0 + bo + 32);
        ldm_x4(bh1, bAddr1 + bo);
        ldm_x4(bl1, bAddr1 + bo + 32);

        // 4 independent chains of depth 3 (group x nt), all live at once.
        float acc0[2][4] = {};
        float acc1[2][4] = {};
        #pragma unroll
        for (int nt = 0; nt < 2; nt++) {
            mma16816(acc0[nt], af[0][0], bh0[2*nt], bh0[2*nt+1]);
            mma16816(acc1[nt], af[1][0], bh1[2*nt], bh1[2*nt+1]);
        }
        #pragma unroll
        for (int nt = 0; nt < 2; nt++) {
            mma16816(acc0[nt], af[0][0], bl0[2*nt], bl0[2*nt+1]);
            mma16816(acc1[nt], af[1][0], bl1[2*nt], bl1[2*nt+1]);
        }
        #pragma unroll
        for (int nt = 0; nt < 2; nt++) {
            mma16816(acc0[nt], af[0][1], bh0[2*nt], bh0[2*nt+1]);
            mma16816(acc1[nt], af[1][1], bh1[2*nt], bh1[2*nt+1]);
        }

        // Epilogue: out = |D1 * D2|, STG.64.
        #pragma unroll
        for (int nt = 0; nt < 2; nt++) {
            int cc = colb + np * 16 + nt * 8;
            float2 v;
            v.x = fabsf(acc0[nt][0] * acc1[nt][0]);
            v.y = fabsf(acc0[nt][1] * acc1[nt][1]);
            *(float2*)(out + rbase * C + cc) = v;
            v.x = fabsf(acc0[nt][2] * acc1[nt][2]);
            v.y = fabsf(acc0[nt][3] * acc1[nt][3]);
            *(float2*)(out + (rbase + 8) * C + cc) = v;
        }
    }
}

extern "C" void kernel_launch(void* const* d_in, const int* in_sizes, int n_in,
                              void* d_out, int out_size) {
    const float* x = (const float*)d_in[0];
    const float* c = (const float*)d_in[1];
    float* out = (float*)d_out;

    int B = in_sizes[0] / 8;   // 8192
    int C = in_sizes[1] / 8;   // 2048
    if (B > BD) B = BD;
    if (C > CD) C = CD;

    int total = B + C;
    qk_pre<<<(total + 127) / 128, 128>>>(x, c, B, C);

    dim3 grid(C / 128, B / 128);
    qk_hmma<<<grid, 512>>>(out, C);
}

// round 7
// speedup vs baseline: 1.0421x; 1.0421x over previous
#include <cuda_runtime.h>
#include <cuda_fp16.h>
#include <cstdint>
#include <math.h>

#define BD 8192
#define CD 2048
#define STRIDE_H 40          // halves per feature row (32 used + 8 pad)
#define STRIDE_B 80          // bytes per row; 80*r mod 128 -> conflict-free

// fp16 hi/lo split features, K=32 storage [hi(16)|lo(16)|pad].
// dot = ah.bh + ah.bl + al.bh  (drops only al.bl ~ 2^-22)
__device__ __align__(16) __half gA[2 * BD * STRIDE_H];
__device__ __align__(16) __half gB[2 * CD * STRIDE_H];

__device__ __forceinline__ uint32_t smem_u32(const void* p) {
    uint32_t a;
    asm("{ .reg .u64 t; cvta.to.shared.u64 t, %1; cvt.u32.u64 %0, t; }" : "=r"(a) : "l"(p));
    return a;
}

// ---------------- Kernel 1: feature precompute ----------------
__global__ void qk_pre(const float* __restrict__ x, const float* __restrict__ c,
                       int B, int C) {
    int t = blockIdx.x * blockDim.x + threadIdx.x;
    if (t >= B + C) return;
    bool isB = t >= B;
    int row = isB ? t - B : t;
    const float* src = (isB ? c : x) + row * 8;

    float cv[8], sv[8];
    #pragma unroll
    for (int j = 0; j < 8; j++) sincosf(0.5f * src[j], &sv[j], &cv[j]);

    float pf[4][4];
    #pragma unroll
    for (int p = 0; p < 4; p++) {
        pf[p][0] = cv[2*p] * cv[2*p+1];
        pf[p][1] = cv[2*p] * sv[2*p+1];
        pf[p][2] = sv[2*p] * cv[2*p+1];
        pf[p][3] = sv[2*p] * sv[2*p+1];
    }

    #pragma unroll
    for (int g = 0; g < 2; g++) {
        __align__(16) __half rowv[STRIDE_H];
        #pragma unroll
        for (int a = 0; a < 4; a++) {
            #pragma unroll
            for (int b = 0; b < 4; b++) {
                float f = pf[2*g][a] * pf[2*g+1][b];
                __half hi = __float2half_rn(f);
                __half lo = __float2half_rn(f - __half2float(hi));
                int i = a * 4 + b;
                rowv[i]      = hi;
                rowv[16 + i] = lo;
            }
        }
        #pragma unroll
        for (int i = 32; i < STRIDE_H; i++) rowv[i] = __float2half_rn(0.f);

        __half* dst = (isB ? gB : gA) + ((size_t)g * (isB ? CD : BD) + row) * STRIDE_H;
        #pragma unroll
        for (int j = 0; j < 5; j++)
            ((uint4*)dst)[j] = ((const uint4*)rowv)[j];
    }
}

// ---------------- Kernel 2: HMMA tile kernel ----------------
// Block 128x128, 8 warps (256 thr), warp tile 32 rows x 64 cols.
// Per 16-col chunk: 4 LDSM up front, then 24 MMAs in 8 independent
// depth-3 chains (group x mt x nt), issued round-robin by k-step.
#define SM_A0 0
#define SM_A1 10240
#define SM_B0 20480
#define SM_B1 30720

__device__ __forceinline__ void ldm_x4(uint32_t* r, uint32_t addr) {
    asm volatile("ldmatrix.sync.aligned.m8n8.x4.shared.b16 {%0,%1,%2,%3}, [%4];"
                 : "=r"(r[0]), "=r"(r[1]), "=r"(r[2]), "=r"(r[3]) : "r"(addr));
}
__device__ __forceinline__ void mma16816(float* d, const uint32_t* a,
                                         uint32_t b0, uint32_t b1) {
    asm volatile(
        "mma.sync.aligned.m16n8k16.row.col.f32.f16.f16.f32 "
        "{%0,%1,%2,%3}, {%4,%5,%6,%7}, {%8,%9}, {%0,%1,%2,%3};"
        : "+f"(d[0]), "+f"(d[1]), "+f"(d[2]), "+f"(d[3])
        : "r"(a[0]), "r"(a[1]), "r"(a[2]), "r"(a[3]), "r"(b0), "r"(b1));
}

__global__ void __launch_bounds__(256, 2)
qk_hmma(float* __restrict__ out, int C) {
    __shared__ __align__(16) unsigned char sm[40960];
    const int tid = threadIdx.x, wid = tid >> 5, lane = tid & 31;
    const int row0 = blockIdx.y * 128, col0 = blockIdx.x * 128;

    // Tile copies: 640 uint4 per array, linear.
    {
        const uint4* s0 = (const uint4*)(gA + (size_t)row0 * STRIDE_H);
        const uint4* s1 = (const uint4*)(gA + (size_t)(BD + row0) * STRIDE_H);
        const uint4* s2 = (const uint4*)(gB + (size_t)col0 * STRIDE_H);
        const uint4* s3 = (const uint4*)(gB + (size_t)(CD + col0) * STRIDE_H);
        uint4* d0 = (uint4*)(sm + SM_A0);
        uint4* d1 = (uint4*)(sm + SM_A1);
        uint4* d2 = (uint4*)(sm + SM_B0);
        uint4* d3 = (uint4*)(sm + SM_B1);
        #pragma unroll
        for (int i = tid; i < 640; i += 256) {
            d0[i] = s0[i]; d1[i] = s1[i]; d2[i] = s2[i]; d3[i] = s3[i];
        }
    }
    __syncthreads();

    const int wr = wid & 3;        // 4 row groups of 32
    const int wc = wid >> 2;       // 2 col groups of 64
    const uint32_t sb = smem_u32(sm);

    // Persistent a-frags: af[g][mt][hl][4], 32 regs.
    uint32_t af[2][2][2][4];
    {
        const uint32_t aoff =
            (uint32_t)(wr * 32 + (lane & 15)) * STRIDE_B + (lane >> 4) * 16;
        #pragma unroll
        for (int mt = 0; mt < 2; mt++)
            #pragma unroll
            for (int hl = 0; hl < 2; hl++) {
                ldm_x4(af[0][mt][hl], sb + SM_A0 + aoff + mt * 16 * STRIDE_B + hl * 32);
                ldm_x4(af[1][mt][hl], sb + SM_A1 + aoff + mt * 16 * STRIDE_B + hl * 32);
            }
    }

    // B ldmatrix base: one x4 covers an nt-pair (16 cols) for one hi/lo half.
    const uint32_t boff =
        (uint32_t)(wc * 64 + (lane & 7) + ((lane >> 4) << 3)) * STRIDE_B +
        ((lane >> 3) & 1) * 16;
    const uint32_t bAddr0 = sb + SM_B0 + boff;
    const uint32_t bAddr1 = sb + SM_B1 + boff;

    const int colb = col0 + wc * 64 + (lane & 3) * 2;
    const size_t rbase = (size_t)(row0 + wr * 32 + (lane >> 2));

    #pragma unroll
    for (int np = 0; np < 4; np++) {   // 16-col chunks
        const uint32_t bo = np * 16 * STRIDE_B;

        // All b-frags up front: both groups, hi+lo (16 regs, 4 LDSM).
        uint32_t bh0[4], bl0[4], bh1[4], bl1[4];
        ldm_x4(bh0, bAddr0 + bo);
        ldm_x4(bl0, bAddr0 + bo + 32);
        ldm_x4(bh1, bAddr1 + bo);
        ldm_x4(bl1, bAddr1 + bo + 32);

        // acc[g][mt][nt][4] : 8 independent chains of depth 3.
        float acc[2][2][2][4] = {};

        // k-step 1: ah . bh   (8 independent MMAs)
        #pragma unroll
        for (int mt = 0; mt < 2; mt++)
            #pragma unroll
            for (int nt = 0; nt < 2; nt++) {
                mma16816(acc[0][mt][nt], af[0][mt][0], bh0[2*nt], bh0[2*nt+1]);
                mma16816(acc[1][mt][nt], af[1][mt][0], bh1[2*nt], bh1[2*nt+1]);
            }
        // k-step 2: ah . bl
        #pragma unroll
        for (int mt = 0; mt < 2; mt++)
            #pragma unroll
            for (int nt = 0; nt < 2; nt++) {
                mma16816(acc[0][mt][nt], af[0][mt][0], bl0[2*nt], bl0[2*nt+1]);
                mma16816(acc[1][mt][nt], af[1][mt][0], bl1[2*nt], bl1[2*nt+1]);
            }
        // k-step 3: al . bh
        #pragma unroll
        for (int mt = 0; mt < 2; mt++)
            #pragma unroll
            for (int nt = 0; nt < 2; nt++) {
                mma16816(acc[0][mt][nt], af[0][mt][1], bh0[2*nt], bh0[2*nt+1]);
                mma16816(acc[1][mt][nt], af[1][mt][1], bh1[2*nt], bh1[2*nt+1]);
            }

        // Epilogue: out = |D1 * D2|, STG.64.
        #pragma unroll
        for (int mt = 0; mt < 2; mt++)
            #pragma unroll
            for (int nt = 0; nt < 2; nt++) {
                size_t rm = rbase + mt * 16;
                int cc = colb + np * 16 + nt * 8;
                float2 v;
                v.x = fabsf(acc[0][mt][nt][0] * acc[1][mt][nt][0]);
                v.y = fabsf(acc[0][mt][nt][1] * acc[1][mt][nt][1]);
                *(float2*)(out + rm * C + cc) = v;
                v.x = fabsf(acc[0][mt][nt][2] * acc[1][mt][nt][2]);
                v.y = fabsf(acc[0][mt][nt][3] * acc[1][mt][nt][3]);
                *(float2*)(out + (rm + 8) * C + cc) = v;
            }
    }
}

extern "C" void kernel_launch(void* const* d_in, const int* in_sizes, int n_in,
                              void* d_out, int out_size) {
    const float* x = (const float*)d_in[0];
    const float* c = (const float*)d_in[1];
    float* out = (float*)d_out;

    int B = in_sizes[0] / 8;   // 8192
    int C = in_sizes[1] / 8;   // 2048
    if (B > BD) B = BD;
    if (C > CD) C = CD;

    int total = B + C;
    qk_pre<<<(total + 127) / 128, 128>>>(x, c, B, C);

    dim3 grid(C / 128, B / 128);
    qk_hmma<<<grid, 256>>>(out, C);
}

// round 8
// speedup vs baseline: 1.1349x; 1.0890x over previous
#include <cuda_runtime.h>
#include <cuda_fp16.h>
#include <cstdint>
#include <math.h>

// Single fused kernel. Block tile 128 rows x 128 cols, 8 warps.
// Features (16 per 4-wire group, unit-norm rows) computed in-block.
// A stored hi+lo fp16 (exact fp32 split), B stored hi only:
//   dot = ah.bh + al.bh = a.bh   (error = a.bl ~ 1e-4 rel, budget 1e-3)
#define STRIDE_A 80        // 32 halves used (hi16|lo16) + pad; 80r mod 128 conflict-free
#define STRIDE_B 48        // 16 halves used (hi16) + pad;    48r mod 128 conflict-free
#define SM_A0 0            // 128*80 = 10240
#define SM_A1 10240
#define SM_B0 20480        // 128*48 = 6144
#define SM_B1 26624
#define SM_TOT 32768

__device__ __forceinline__ uint32_t smem_u32(const void* p) {
    uint32_t a;
    asm("{ .reg .u64 t; cvta.to.shared.u64 t, %1; cvt.u32.u64 %0, t; }" : "=r"(a) : "l"(p));
    return a;
}
__device__ __forceinline__ void ldm_x4(uint32_t* r, uint32_t addr) {
    asm volatile("ldmatrix.sync.aligned.m8n8.x4.shared.b16 {%0,%1,%2,%3}, [%4];"
                 : "=r"(r[0]), "=r"(r[1]), "=r"(r[2]), "=r"(r[3]) : "r"(addr));
}
__device__ __forceinline__ void mma16816(float* d, const uint32_t* a,
                                         uint32_t b0, uint32_t b1) {
    asm volatile(
        "mma.sync.aligned.m16n8k16.row.col.f32.f16.f16.f32 "
        "{%0,%1,%2,%3}, {%4,%5,%6,%7}, {%8,%9}, {%0,%1,%2,%3};"
        : "+f"(d[0]), "+f"(d[1]), "+f"(d[2]), "+f"(d[3])
        : "r"(a[0]), "r"(a[1]), "r"(a[2]), "r"(a[3]), "r"(b0), "r"(b1));
}

__global__ void __launch_bounds__(256, 2)
qk_fused(const float* __restrict__ x, const float* __restrict__ c,
         float* __restrict__ out, int C) {
    __shared__ __align__(16) unsigned char sm[SM_TOT];
    const int tid = threadIdx.x, wid = tid >> 5, lane = tid & 31;
    const int row0 = blockIdx.y * 128, col0 = blockIdx.x * 128;
    const uint32_t sb = smem_u32(sm);

    // ---- Fused feature prologue: tid<128 -> A row, tid>=128 -> B col ----
    {
        const int r = tid & 127;
        const bool isB = tid >= 128;
        const float* src = isB ? (c + (size_t)(col0 + r) * 8)
                               : (x + (size_t)(row0 + r) * 8);
        float cv[8], sv[8];
        #pragma unroll
        for (int j = 0; j < 8; j++) sincosf(0.5f * src[j], &sv[j], &cv[j]);

        float pf[4][4];
        #pragma unroll
        for (int p = 0; p < 4; p++) {
            pf[p][0] = cv[2*p] * cv[2*p+1];
            pf[p][1] = cv[2*p] * sv[2*p+1];
            pf[p][2] = sv[2*p] * cv[2*p+1];
            pf[p][3] = sv[2*p] * sv[2*p+1];
        }
        #pragma unroll
        for (int g = 0; g < 2; g++) {
            if (!isB) {
                __align__(16) __half v[32];   // hi[16] | lo[16]
                #pragma unroll
                for (int a = 0; a < 4; a++)
                    #pragma unroll
                    for (int b = 0; b < 4; b++) {
                        float f = pf[2*g][a] * pf[2*g+1][b];
                        __half hi = __float2half_rn(f);
                        v[a*4+b]      = hi;
                        v[16 + a*4+b] = __float2half_rn(f - __half2float(hi));
                    }
                uint4* dst = (uint4*)(sm + (g ? SM_A1 : SM_A0) + r * STRIDE_A);
                #pragma unroll
                for (int j = 0; j < 4; j++) dst[j] = ((const uint4*)v)[j];
            } else {
                __align__(16) __half v[16];   // hi only
                #pragma unroll
                for (int a = 0; a < 4; a++)
                    #pragma unroll
                    for (int b = 0; b < 4; b++)
                        v[a*4+b] = __float2half_rn(pf[2*g][a] * pf[2*g+1][b]);
                uint4* dst = (uint4*)(sm + (g ? SM_B1 : SM_B0) + r * STRIDE_B);
                dst[0] = ((const uint4*)v)[0];
                dst[1] = ((const uint4*)v)[1];
            }
        }
    }
    __syncthreads();

    // ---- MMA mainloop: warp tile 32 rows x 64 cols ----
    const int wr = wid & 3;        // 4 row groups of 32
    const int wc = wid >> 2;       // 2 col groups of 64

    // Persistent a-frags: af[g][mt][hl][4], 32 regs.
    uint32_t af[2][2][2][4];
    {
        const uint32_t aoff =
            (uint32_t)(wr * 32 + (lane & 15)) * STRIDE_A + (lane >> 4) * 16;
        #pragma unroll
        for (int mt = 0; mt < 2; mt++)
            #pragma unroll
            for (int hl = 0; hl < 2; hl++) {
                ldm_x4(af[0][mt][hl], sb + SM_A0 + aoff + mt * 16 * STRIDE_A + hl * 32);
                ldm_x4(af[1][mt][hl], sb + SM_A1 + aoff + mt * 16 * STRIDE_A + hl * 32);
            }
    }

    // B ldmatrix base: one x4 covers an nt-pair (16 cols), hi only.
    const uint32_t boff =
        (uint32_t)(wc * 64 + (lane & 7) + ((lane >> 4) << 3)) * STRIDE_B +
        ((lane >> 3) & 1) * 16;
    const uint32_t bAddr0 = sb + SM_B0 + boff;
    const uint32_t bAddr1 = sb + SM_B1 + boff;

    const int colb = col0 + wc * 64 + (lane & 3) * 2;
    const size_t rbase = (size_t)(row0 + wr * 32 + (lane >> 2));

    #pragma unroll
    for (int np = 0; np < 4; np++) {   // 16-col chunks
        const uint32_t bo = np * 16 * STRIDE_B;

        uint32_t b0[4], b1[4];
        ldm_x4(b0, bAddr0 + bo);
        ldm_x4(b1, bAddr1 + bo);

        // acc[g][mt][nt][4] : 8 independent chains of depth 2.
        float acc[2][2][2][4] = {};

        // k-step 1: ah . bh  (8 independent MMAs)
        #pragma unroll
        for (int mt = 0; mt < 2; mt++)
            #pragma unroll
            for (int nt = 0; nt < 2; nt++) {
                mma16816(acc[0][mt][nt], af[0][mt][0], b0[2*nt], b0[2*nt+1]);
                mma16816(acc[1][mt][nt], af[1][mt][0], b1[2*nt], b1[2*nt+1]);
            }
        // k-step 2: al . bh
        #pragma unroll
        for (int mt = 0; mt < 2; mt++)
            #pragma unroll
            for (int nt = 0; nt < 2; nt++) {
                mma16816(acc[0][mt][nt], af[0][mt][1], b0[2*nt], b0[2*nt+1]);
                mma16816(acc[1][mt][nt], af[1][mt][1], b1[2*nt], b1[2*nt+1]);
            }

        // Epilogue: out = |D1 * D2|
        #pragma unroll
        for (int mt = 0; mt < 2; mt++)
            #pragma unroll
            for (int nt = 0; nt < 2; nt++) {
                size_t rm = rbase + mt * 16;
                int cc = colb + np * 16 + nt * 8;
                float2 v;
                v.x = fabsf(acc[0][mt][nt][0] * acc[1][mt][nt][0]);
                v.y = fabsf(acc[0][mt][nt][1] * acc[1][mt][nt][1]);
                *(float2*)(out + rm * C + cc) = v;
                v.x = fabsf(acc[0][mt][nt][2] * acc[1][mt][nt][2]);
                v.y = fabsf(acc[0][mt][nt][3] * acc[1][mt][nt][3]);
                *(float2*)(out + (rm + 8) * C + cc) = v;
            }
    }
}

extern "C" void kernel_launch(void* const* d_in, const int* in_sizes, int n_in,
                              void* d_out, int out_size) {
    const float* x = (const float*)d_in[0];
    const float* c = (const float*)d_in[1];
    float* out = (float*)d_out;

    int B = in_sizes[0] / 8;   // 8192
    int C = in_sizes[1] / 8;   // 2048

    dim3 grid(C / 128, B / 128);
    qk_fused<<<grid, 256>>>(x, c, out, C);
}